// round 1
// baseline (speedup 1.0000x reference)
#include <cuda_runtime.h>
#include <cuda_bf16.h>

// SE3 Hamiltonian NODE dynamics: per-row map over [BS, 22] f32.
// Layout per row:
//   [0:3)   x        (unused)
//   [3:12)  R        (row-major 3x3)
//   [12:15) qdv
//   [15:18) qdw
//   [18:22) u
// Output per row:
//   [0:3)   dx = R @ dHdpv
//   [3:12)  dR = [cross(R0,gw), cross(R1,gw), cross(R2,gw)]
//   [12:15) dv
//   [15:18) dw
//   [18:22) zeros

#define ROWS_PER_BLK 128
#define TPB          128
#define ROW_F        22
#define CHUNK        (ROWS_PER_BLK * ROW_F)   // 2816 floats = 11264 bytes
#define CHUNK4       (CHUNK / 4)              // 704 float4

// Constants folded at compile time from the same double expressions the
// reference uses (then rounded to f32, matching jnp.float32 casts).
#define M1c    ((float)(1.0 / (1.0 / 0.027)))      // M1 diag (== 0.027)
#define M1INVc ((float)(1.0 / 0.027))              // M1_INV diag
#define J0c    ((float)(2.3951e-05))               // J diag xy
#define J2c    ((float)(3.2347e-05))               // J diag z
#define JI0c   ((float)(1.0 / 2.3951e-05))         // J^-1 diag xy
#define JI2c   ((float)(1.0 / 3.2347e-05))         // J^-1 diag z
#define MGc    ((float)(0.027 * 9.81))

__device__ __forceinline__ void se3_row_compute(const float* __restrict__ v,
                                                float* __restrict__ o) {
    const float R00 = v[3],  R01 = v[4],  R02 = v[5];
    const float R10 = v[6],  R11 = v[7],  R12 = v[8];
    const float R20 = v[9],  R21 = v[10], R22 = v[11];

    const float pv0 = v[12] * M1c, pv1 = v[13] * M1c, pv2 = v[14] * M1c;
    const float pw0 = v[15] * J0c, pw1 = v[16] * J0c, pw2 = v[17] * J2c;

    const float gv0 = pv0 * M1INVc, gv1 = pv1 * M1INVc, gv2 = pv2 * M1INVc;
    const float gw0 = pw0 * JI0c,   gw1 = pw1 * JI0c,   gw2 = pw2 * JI2c;

    // dx = R @ gv
    o[0] = R00 * gv0 + R01 * gv1 + R02 * gv2;
    o[1] = R10 * gv0 + R11 * gv1 + R12 * gv2;
    o[2] = R20 * gv0 + R21 * gv1 + R22 * gv2;

    // dR rows: cross(R_row_i, gw)
    o[3]  = R01 * gw2 - R02 * gw1;
    o[4]  = R02 * gw0 - R00 * gw2;
    o[5]  = R00 * gw1 - R01 * gw0;
    o[6]  = R11 * gw2 - R12 * gw1;
    o[7]  = R12 * gw0 - R10 * gw2;
    o[8]  = R10 * gw1 - R11 * gw0;
    o[9]  = R21 * gw2 - R22 * gw1;
    o[10] = R22 * gw0 - R20 * gw2;
    o[11] = R20 * gw1 - R21 * gw0;

    // dpv = cross(pv, gw) - MG * R_row2 + (0, 0, u0)
    const float dpv0 = (pv1 * gw2 - pv2 * gw1) - MGc * R20;
    const float dpv1 = (pv2 * gw0 - pv0 * gw2) - MGc * R21;
    const float dpv2 = (pv0 * gw1 - pv1 * gw0) - MGc * R22 + v[18];

    // dpw = cross(pw, gw) + cross(pv, gv) + u[1:4]
    const float dpw0 = (pw1 * gw2 - pw2 * gw1) + (pv1 * gv2 - pv2 * gv1) + v[19];
    const float dpw1 = (pw2 * gw0 - pw0 * gw2) + (pv2 * gv0 - pv0 * gv2) + v[20];
    const float dpw2 = (pw0 * gw1 - pw1 * gw0) + (pv0 * gv1 - pv1 * gv0) + v[21];

    // dv = dpv * M1_INV, dw = dpw * J^-1
    o[12] = dpv0 * M1INVc;
    o[13] = dpv1 * M1INVc;
    o[14] = dpv2 * M1INVc;
    o[15] = dpw0 * JI0c;
    o[16] = dpw1 * JI0c;
    o[17] = dpw2 * JI2c;

    o[18] = 0.0f; o[19] = 0.0f; o[20] = 0.0f; o[21] = 0.0f;
}

__global__ __launch_bounds__(TPB)
void SE3HamNODEGT_kernel(const float* __restrict__ in, float* __restrict__ out,
                         int nrows) {
    __shared__ float s[CHUNK];
    const long long base_row = (long long)blockIdx.x * ROWS_PER_BLK;
    const long long base_elem = base_row * ROW_F;

    const bool full = (base_row + ROWS_PER_BLK) <= (long long)nrows;

    if (full) {
        // Coalesced float4 gmem -> smem
        const float4* __restrict__ gin = reinterpret_cast<const float4*>(in + base_elem);
        float4* sv = reinterpret_cast<float4*>(s);
        #pragma unroll
        for (int i = threadIdx.x; i < CHUNK4; i += TPB)
            sv[i] = gin[i];
        __syncthreads();

        float v[ROW_F], o[ROW_F];
        #pragma unroll
        for (int j = 0; j < ROW_F; j++) v[j] = s[threadIdx.x * ROW_F + j];

        se3_row_compute(v, o);

        __syncthreads();
        #pragma unroll
        for (int j = 0; j < ROW_F; j++) s[threadIdx.x * ROW_F + j] = o[j];
        __syncthreads();

        float4* __restrict__ gout = reinterpret_cast<float4*>(out + base_elem);
        #pragma unroll
        for (int i = threadIdx.x; i < CHUNK4; i += TPB)
            gout[i] = sv[i];
    } else {
        // Tail block: scalar guarded path (not hit for BS=2e6, kept for safety)
        const long long total = (long long)nrows * ROW_F;
        for (int i = threadIdx.x; i < CHUNK; i += TPB) {
            long long g = base_elem + i;
            if (g < total) s[i] = in[g];
        }
        __syncthreads();

        const long long row = base_row + threadIdx.x;
        float v[ROW_F], o[ROW_F];
        if (row < nrows) {
            #pragma unroll
            for (int j = 0; j < ROW_F; j++) v[j] = s[threadIdx.x * ROW_F + j];
            se3_row_compute(v, o);
        }
        __syncthreads();
        if (row < nrows) {
            #pragma unroll
            for (int j = 0; j < ROW_F; j++) s[threadIdx.x * ROW_F + j] = o[j];
        }
        __syncthreads();

        for (int i = threadIdx.x; i < CHUNK; i += TPB) {
            long long g = base_elem + i;
            if (g < total) out[g] = s[i];
        }
    }
}

extern "C" void kernel_launch(void* const* d_in, const int* in_sizes, int n_in,
                              void* d_out, int out_size) {
    // Inputs: {'t': scalar, 'input': [BS, 22] f32}. Pick the big one robustly.
    const float* in = nullptr;
    for (int i = 0; i < n_in; i++) {
        if (in_sizes[i] == out_size) { in = (const float*)d_in[i]; break; }
    }
    if (!in) {
        // fallback: largest input
        int best = 0;
        for (int i = 1; i < n_in; i++) if (in_sizes[i] > in_sizes[best]) best = i;
        in = (const float*)d_in[best];
    }

    const int nrows = out_size / ROW_F;
    const int blocks = (nrows + ROWS_PER_BLK - 1) / ROWS_PER_BLK;
    SE3HamNODEGT_kernel<<<blocks, TPB>>>(in, (float*)d_out, nrows);
}

// round 2
// speedup vs baseline: 1.0006x; 1.0006x over previous
#include <cuda_runtime.h>
#include <cuda_bf16.h>

// SE3 Hamiltonian NODE dynamics: per-row map over [BS, 22] f32.
// HBM-bound streaming kernel: float4-coalesced gmem<->smem staging,
// conflict-free float2 smem row access, 2 barriers, streaming cache hints.

#define ROWS_PER_BLK 128
#define TPB          128
#define ROW_F        22
#define ROW_F2       11                        // float2 per row
#define CHUNK        (ROWS_PER_BLK * ROW_F)    // 2816 floats = 11264 B
#define CHUNK4       (CHUNK / 4)               // 704 float4

// Constants folded at compile time from the same double expressions the
// reference uses (rounded to f32, matching jnp.float32 casts).
#define M1c    ((float)(1.0 / (1.0 / 0.027)))
#define M1INVc ((float)(1.0 / 0.027))
#define J0c    ((float)(2.3951e-05))
#define J2c    ((float)(3.2347e-05))
#define JI0c   ((float)(1.0 / 2.3951e-05))
#define JI2c   ((float)(1.0 / 3.2347e-05))
#define MGc    ((float)(0.027 * 9.81))

__device__ __forceinline__ void se3_row_compute(const float* __restrict__ v,
                                                float* __restrict__ o) {
    const float R00 = v[3],  R01 = v[4],  R02 = v[5];
    const float R10 = v[6],  R11 = v[7],  R12 = v[8];
    const float R20 = v[9],  R21 = v[10], R22 = v[11];

    const float pv0 = v[12] * M1c, pv1 = v[13] * M1c, pv2 = v[14] * M1c;
    const float pw0 = v[15] * J0c, pw1 = v[16] * J0c, pw2 = v[17] * J2c;

    const float gv0 = pv0 * M1INVc, gv1 = pv1 * M1INVc, gv2 = pv2 * M1INVc;
    const float gw0 = pw0 * JI0c,   gw1 = pw1 * JI0c,   gw2 = pw2 * JI2c;

    // dx = R @ gv
    o[0] = R00 * gv0 + R01 * gv1 + R02 * gv2;
    o[1] = R10 * gv0 + R11 * gv1 + R12 * gv2;
    o[2] = R20 * gv0 + R21 * gv1 + R22 * gv2;

    // dR rows: cross(R_row_i, gw)
    o[3]  = R01 * gw2 - R02 * gw1;
    o[4]  = R02 * gw0 - R00 * gw2;
    o[5]  = R00 * gw1 - R01 * gw0;
    o[6]  = R11 * gw2 - R12 * gw1;
    o[7]  = R12 * gw0 - R10 * gw2;
    o[8]  = R10 * gw1 - R11 * gw0;
    o[9]  = R21 * gw2 - R22 * gw1;
    o[10] = R22 * gw0 - R20 * gw2;
    o[11] = R20 * gw1 - R21 * gw0;

    // dpv = cross(pv, gw) - MG * R_row2 + (0, 0, u0)
    const float dpv0 = (pv1 * gw2 - pv2 * gw1) - MGc * R20;
    const float dpv1 = (pv2 * gw0 - pv0 * gw2) - MGc * R21;
    const float dpv2 = (pv0 * gw1 - pv1 * gw0) - MGc * R22 + v[18];

    // dpw = cross(pw, gw) + cross(pv, gv) + u[1:4]
    const float dpw0 = (pw1 * gw2 - pw2 * gw1) + (pv1 * gv2 - pv2 * gv1) + v[19];
    const float dpw1 = (pw2 * gw0 - pw0 * gw2) + (pv2 * gv0 - pv0 * gv2) + v[20];
    const float dpw2 = (pw0 * gw1 - pw1 * gw0) + (pv0 * gv1 - pv1 * gv0) + v[21];

    o[12] = dpv0 * M1INVc;
    o[13] = dpv1 * M1INVc;
    o[14] = dpv2 * M1INVc;
    o[15] = dpw0 * JI0c;
    o[16] = dpw1 * JI0c;
    o[17] = dpw2 * JI2c;

    o[18] = 0.0f; o[19] = 0.0f; o[20] = 0.0f; o[21] = 0.0f;
}

__device__ __forceinline__ float4 ldg_cs4(const float4* p) {
    float4 r;
    asm volatile("ld.global.cs.v4.f32 {%0,%1,%2,%3}, [%4];"
                 : "=f"(r.x), "=f"(r.y), "=f"(r.z), "=f"(r.w) : "l"(p));
    return r;
}
__device__ __forceinline__ void stg_cs4(float4* p, float4 v) {
    asm volatile("st.global.cs.v4.f32 [%0], {%1,%2,%3,%4};"
                 :: "l"(p), "f"(v.x), "f"(v.y), "f"(v.z), "f"(v.w));
}

__global__ __launch_bounds__(TPB)
void SE3HamNODEGT_kernel(const float* __restrict__ in, float* __restrict__ out,
                         int nrows) {
    __shared__ float s[CHUNK];
    const long long base_row  = (long long)blockIdx.x * ROWS_PER_BLK;
    const long long base_elem = base_row * ROW_F;

    const bool full = (base_row + ROWS_PER_BLK) <= (long long)nrows;

    if (full) {
        // Coalesced float4 gmem -> smem (streaming, evict-first)
        const float4* __restrict__ gin = reinterpret_cast<const float4*>(in + base_elem);
        float4* sv = reinterpret_cast<float4*>(s);
        #pragma unroll
        for (int i = threadIdx.x; i < CHUNK4; i += TPB)
            sv[i] = ldg_cs4(gin + i);
        __syncthreads();

        // Conflict-free float2 row read: row start word = t*22 (8B aligned),
        // LDS.64 phases of 16 lanes hit 16 distinct even banks + 16 odd banks.
        float v[ROW_F], o[ROW_F];
        {
            const float2* s2 = reinterpret_cast<const float2*>(s) + threadIdx.x * ROW_F2;
            #pragma unroll
            for (int k = 0; k < ROW_F2; k++) {
                float2 t = s2[k];
                v[2 * k] = t.x;
                v[2 * k + 1] = t.y;
            }
        }

        se3_row_compute(v, o);

        // Write back into own row region only (no cross-thread hazard -> no sync)
        {
            float2* s2 = reinterpret_cast<float2*>(s) + threadIdx.x * ROW_F2;
            #pragma unroll
            for (int k = 0; k < ROW_F2; k++)
                s2[k] = make_float2(o[2 * k], o[2 * k + 1]);
        }
        __syncthreads();

        // Coalesced float4 smem -> gmem (streaming)
        float4* __restrict__ gout = reinterpret_cast<float4*>(out + base_elem);
        #pragma unroll
        for (int i = threadIdx.x; i < CHUNK4; i += TPB)
            stg_cs4(gout + i, sv[i]);
    } else {
        // Tail block: scalar guarded path (not hit for BS=2e6; kept for safety)
        const long long total = (long long)nrows * ROW_F;
        for (int i = threadIdx.x; i < CHUNK; i += TPB) {
            long long g = base_elem + i;
            if (g < total) s[i] = in[g];
        }
        __syncthreads();

        const long long row = base_row + threadIdx.x;
        float v[ROW_F], o[ROW_F];
        if (row < nrows) {
            #pragma unroll
            for (int j = 0; j < ROW_F; j++) v[j] = s[threadIdx.x * ROW_F + j];
            se3_row_compute(v, o);
            #pragma unroll
            for (int j = 0; j < ROW_F; j++) s[threadIdx.x * ROW_F + j] = o[j];
        }
        __syncthreads();

        for (int i = threadIdx.x; i < CHUNK; i += TPB) {
            long long g = base_elem + i;
            if (g < total) out[g] = s[i];
        }
    }
}

extern "C" void kernel_launch(void* const* d_in, const int* in_sizes, int n_in,
                              void* d_out, int out_size) {
    const float* in = nullptr;
    for (int i = 0; i < n_in; i++) {
        if (in_sizes[i] == out_size) { in = (const float*)d_in[i]; break; }
    }
    if (!in) {
        int best = 0;
        for (int i = 1; i < n_in; i++) if (in_sizes[i] > in_sizes[best]) best = i;
        in = (const float*)d_in[best];
    }

    const int nrows = out_size / ROW_F;
    const int blocks = (nrows + ROWS_PER_BLK - 1) / ROWS_PER_BLK;
    SE3HamNODEGT_kernel<<<blocks, TPB>>>(in, (float*)d_out, nrows);
}